// round 1
// baseline (speedup 1.0000x reference)
#include <cuda_runtime.h>
#include <cuda_bf16.h>
#include <math.h>

// Problem dims (fixed by the dataset)
#define BATCH 8
#define SEQ   2048
#define DIM   1024
#define BN_ROWS (BATCH * SEQ)   // 16384

// ------------------------- scratch (no allocs allowed) -------------------------
__device__ float g_q[BATCH * SEQ * DIM];   // 67 MB
__device__ float g_k[BATCH * SEQ * DIM];   // 67 MB
__device__ float g_v[BATCH * SEQ * DIM];   // 67 MB
__device__ float g_s[(long long)BATCH * SEQ * SEQ]; // 134 MB scores/probs

// ------------------------- SGEMM: C = A @ B (+bias), optional B^T ---------------
// Tiles: 128x128 output, K-chunk 8, 256 threads, 8x8 per-thread microtile.
// TRANSB=false: B is [K, Nn] row-major (NN). TRANSB=true: B is [Nn, K] row-major (NT).
template <bool TRANSB>
__global__ __launch_bounds__(256, 2)
void sgemm_kernel(const float* __restrict__ A, const float* __restrict__ Bm,
                  const float* __restrict__ bias, float* __restrict__ C,
                  int M, int Nn, int K,
                  long long sA, long long sB, long long sC)
{
    const long long bz = blockIdx.z;
    A  += bz * sA;
    Bm += bz * sB;
    C  += bz * sC;

    __shared__ float As[8][128];
    __shared__ float Bs[8][128];

    const int tid = threadIdx.x;
    const int rowBase = blockIdx.y * 128;
    const int colBase = blockIdx.x * 128;
    const int tx = tid & 15;        // 0..15  -> column micro-tile
    const int ty = tid >> 4;        // 0..15  -> row micro-tile

    // A-tile loader: 128 rows x 8 cols, one float4 per thread
    const int aRow  = tid >> 1;     // 0..127
    const int aCol4 = tid & 1;      // 0..1   (float4 index within the 8-wide k chunk)
    // B-tile loader (NN): 8 rows x 128 cols, one float4 per thread
    const int bRow  = tid >> 5;     // 0..7
    const int bCol4 = tid & 31;     // 0..31

    float acc[8][8];
#pragma unroll
    for (int i = 0; i < 8; i++)
#pragma unroll
        for (int j = 0; j < 8; j++) acc[i][j] = 0.f;

    for (int k0 = 0; k0 < K; k0 += 8) {
        // load A tile (transposed into As[k][m])
        float4 va = *(const float4*)(A + (long long)(rowBase + aRow) * K + (k0 + aCol4 * 4));
        As[aCol4 * 4 + 0][aRow] = va.x;
        As[aCol4 * 4 + 1][aRow] = va.y;
        As[aCol4 * 4 + 2][aRow] = va.z;
        As[aCol4 * 4 + 3][aRow] = va.w;

        if (TRANSB) {
            // B rows are the output-column dim; k contiguous
            float4 vb = *(const float4*)(Bm + (long long)(colBase + aRow) * K + (k0 + aCol4 * 4));
            Bs[aCol4 * 4 + 0][aRow] = vb.x;
            Bs[aCol4 * 4 + 1][aRow] = vb.y;
            Bs[aCol4 * 4 + 2][aRow] = vb.z;
            Bs[aCol4 * 4 + 3][aRow] = vb.w;
        } else {
            float4 vb = *(const float4*)(Bm + (long long)(k0 + bRow) * Nn + (colBase + bCol4 * 4));
            *(float4*)&Bs[bRow][bCol4 * 4] = vb;
        }
        __syncthreads();

#pragma unroll
        for (int kk = 0; kk < 8; kk++) {
            float4 a0 = *(const float4*)&As[kk][ty * 8];
            float4 a1 = *(const float4*)&As[kk][ty * 8 + 4];
            float4 b0 = *(const float4*)&Bs[kk][tx * 8];
            float4 b1 = *(const float4*)&Bs[kk][tx * 8 + 4];
            float a[8] = {a0.x, a0.y, a0.z, a0.w, a1.x, a1.y, a1.z, a1.w};
            float b[8] = {b0.x, b0.y, b0.z, b0.w, b1.x, b1.y, b1.z, b1.w};
#pragma unroll
            for (int i = 0; i < 8; i++)
#pragma unroll
                for (int j = 0; j < 8; j++)
                    acc[i][j] = fmaf(a[i], b[j], acc[i][j]);
        }
        __syncthreads();
    }

    // epilogue
    float bvals[8];
#pragma unroll
    for (int j = 0; j < 8; j++)
        bvals[j] = bias ? bias[colBase + tx * 8 + j] : 0.f;

#pragma unroll
    for (int i = 0; i < 8; i++) {
        const long long crow = (long long)(rowBase + ty * 8 + i) * Nn + colBase + tx * 8;
        float4 o0, o1;
        o0.x = acc[i][0] + bvals[0]; o0.y = acc[i][1] + bvals[1];
        o0.z = acc[i][2] + bvals[2]; o0.w = acc[i][3] + bvals[3];
        o1.x = acc[i][4] + bvals[4]; o1.y = acc[i][5] + bvals[5];
        o1.z = acc[i][6] + bvals[6]; o1.w = acc[i][7] + bvals[7];
        *(float4*)(C + crow)     = o0;
        *(float4*)(C + crow + 4) = o1;
    }
}

// ------------------------- row softmax with fused 1/sqrt(D) scale ----------------
__global__ void softmax_kernel(float* __restrict__ S)
{
    const long long row = blockIdx.x;
    float* p = S + row * (long long)SEQ;
    const int t = threadIdx.x;   // 256 threads, 8 elems each

    __shared__ float shm[32];
    __shared__ float shs[32];

    const float scale = 0.03125f;  // 1/sqrt(1024)
    float v[8];
    float mx = -INFINITY;
#pragma unroll
    for (int i = 0; i < 8; i++) {
        v[i] = p[t + i * 256] * scale;
        mx = fmaxf(mx, v[i]);
    }
    // block-reduce max
#pragma unroll
    for (int o = 16; o; o >>= 1) mx = fmaxf(mx, __shfl_xor_sync(0xffffffffu, mx, o));
    if ((t & 31) == 0) shm[t >> 5] = mx;
    __syncthreads();
    if (t == 0) {
        float m = shm[0];
#pragma unroll
        for (int w = 1; w < 8; w++) m = fmaxf(m, shm[w]);
        shm[0] = m;
    }
    __syncthreads();
    mx = shm[0];

    float sum = 0.f;
#pragma unroll
    for (int i = 0; i < 8; i++) {
        v[i] = expf(v[i] - mx);
        sum += v[i];
    }
#pragma unroll
    for (int o = 16; o; o >>= 1) sum += __shfl_xor_sync(0xffffffffu, sum, o);
    if ((t & 31) == 0) shs[t >> 5] = sum;
    __syncthreads();
    if (t == 0) {
        float s = 0.f;
#pragma unroll
        for (int w = 0; w < 8; w++) s += shs[w];
        shs[0] = s;
    }
    __syncthreads();
    const float inv = 1.0f / shs[0];

#pragma unroll
    for (int i = 0; i < 8; i++) p[t + i * 256] = v[i] * inv;
}

// ------------------------- launch -------------------------
extern "C" void kernel_launch(void* const* d_in, const int* in_sizes, int n_in,
                              void* d_out, int out_size)
{
    const float* x  = (const float*)d_in[0];
    const float* Wq = (const float*)d_in[1];
    const float* bq = (const float*)d_in[2];
    const float* Wk = (const float*)d_in[3];
    const float* bk = (const float*)d_in[4];
    const float* Wv = (const float*)d_in[5];
    const float* bv = (const float*)d_in[6];
    float* out = (float*)d_out;

    float *q, *k, *v, *s;
    cudaGetSymbolAddress((void**)&q, g_q);
    cudaGetSymbolAddress((void**)&k, g_k);
    cudaGetSymbolAddress((void**)&v, g_v);
    cudaGetSymbolAddress((void**)&s, g_s);

    const dim3 blk(256);
    const long long sQK = (long long)SEQ * DIM;   // per-batch q/k/v stride
    const long long sSS = (long long)SEQ * SEQ;   // per-batch scores stride

    // QKV projections: [16384,1024] @ [1024,1024] + bias  (NN)
    {
        dim3 g(DIM / 128, BN_ROWS / 128, 1);   // (8, 128, 1)
        sgemm_kernel<false><<<g, blk>>>(x, Wq, bq, q, BN_ROWS, DIM, DIM, 0, 0, 0);
        sgemm_kernel<false><<<g, blk>>>(x, Wk, bk, k, BN_ROWS, DIM, DIM, 0, 0, 0);
        sgemm_kernel<false><<<g, blk>>>(x, Wv, bv, v, BN_ROWS, DIM, DIM, 0, 0, 0);
    }

    // scores = Q @ K^T per batch  (NT), [2048,1024] x [2048,1024]^T
    {
        dim3 g(SEQ / 128, SEQ / 128, BATCH);   // (16, 16, 8)
        sgemm_kernel<true><<<g, blk>>>(q, k, nullptr, s, SEQ, SEQ, DIM, sQK, sQK, sSS);
    }

    // softmax over last dim with 1/32 scale
    softmax_kernel<<<BATCH * SEQ, 256>>>(s);

    // out = P @ V per batch  (NN), [2048,2048] x [2048,1024]
    {
        dim3 g(DIM / 128, SEQ / 128, BATCH);   // (8, 16, 8)
        sgemm_kernel<false><<<g, blk>>>(s, v, nullptr, out, SEQ, DIM, SEQ, sSS, sQK, sQK);
    }
}

// round 4
// speedup vs baseline: 3.1661x; 3.1661x over previous
#include <cuda_runtime.h>
#include <cuda_bf16.h>
#include <cstdint>
#include <math.h>

#define BATCH 8
#define SEQ   2048
#define DIM   1024
#define BN_ROWS (BATCH * SEQ)     // 16384

// ---------------- tile config ----------------
#define TMt 128
#define TNt 128
#define TKt 64                     // bf16 per k-chunk (128B rows, SW128)

static constexpr int TILE_BYTES  = TMt * 128;          // 16384 (one matrix)
static constexpr int OFF_AH = 0;
static constexpr int OFF_AL = 16384;
static constexpr int OFF_BH = 32768;
static constexpr int OFF_BL = 49152;
static constexpr int STAGE_BYTES = 65536;
static constexpr int NSTAGE = 3;
static constexpr int SMEM_TOTAL = NSTAGE * STAGE_BYTES;  // 196608

// ---------------- scratch (__device__ globals; no allocs allowed) --------------
__device__ __nv_bfloat16 g_xh[(long long)BN_ROWS * DIM];
__device__ __nv_bfloat16 g_xl[(long long)BN_ROWS * DIM];
__device__ __nv_bfloat16 g_wth[3u * DIM * DIM];
__device__ __nv_bfloat16 g_wtl[3u * DIM * DIM];
__device__ __nv_bfloat16 g_qh[(long long)BN_ROWS * DIM];
__device__ __nv_bfloat16 g_ql[(long long)BN_ROWS * DIM];
__device__ __nv_bfloat16 g_kh[(long long)BN_ROWS * DIM];
__device__ __nv_bfloat16 g_kl[(long long)BN_ROWS * DIM];
__device__ __nv_bfloat16 g_vth[(long long)BATCH * DIM * SEQ];  // [b][dim][seq]
__device__ __nv_bfloat16 g_vtl[(long long)BATCH * DIM * SEQ];
__device__ float         g_s [(long long)BATCH * SEQ * SEQ];    // fp32 scores
__device__ __nv_bfloat16 g_ph[(long long)BATCH * SEQ * SEQ];
__device__ __nv_bfloat16 g_pl[(long long)BATCH * SEQ * SEQ];

// ---------------- PTX helpers ----------------
__device__ __forceinline__ uint32_t smem_u32(const void* p) {
    uint32_t a;
    asm("{ .reg .u64 t; cvta.to.shared.u64 t, %1; cvt.u32.u64 %0, t; }" : "=r"(a) : "l"(p));
    return a;
}
__device__ __forceinline__ void cp16(uint32_t saddr, const void* g) {
    asm volatile("cp.async.cg.shared.global [%0], [%1], 16;" :: "r"(saddr), "l"(g));
}
#define CP_COMMIT() asm volatile("cp.async.commit_group;" ::: "memory")
#define CP_WAIT1()  asm volatile("cp.async.wait_group 1;" ::: "memory")
#define CP_WAIT0()  asm volatile("cp.async.wait_group 0;" ::: "memory")

__device__ __forceinline__ void ldsm_x4(uint32_t (&r)[4], uint32_t addr) {
    asm volatile("ldmatrix.sync.aligned.m8n8.x4.shared.b16 {%0,%1,%2,%3}, [%4];"
        : "=r"(r[0]), "=r"(r[1]), "=r"(r[2]), "=r"(r[3]) : "r"(addr));
}
__device__ __forceinline__ void mma_16816(float (&d)[4], const uint32_t (&a)[4],
                                          uint32_t b0, uint32_t b1) {
    asm volatile("mma.sync.aligned.m16n8k16.row.col.f32.bf16.bf16.f32 "
        "{%0,%1,%2,%3}, {%4,%5,%6,%7}, {%8,%9}, {%0,%1,%2,%3};"
        : "+f"(d[0]), "+f"(d[1]), "+f"(d[2]), "+f"(d[3])
        : "r"(a[0]), "r"(a[1]), "r"(a[2]), "r"(a[3]), "r"(b0), "r"(b1));
}
__device__ __forceinline__ uint32_t sw128(uint32_t off) {
    return off ^ (((off >> 7) & 7) << 4);
}

// ---------------- unified split-bf16 mma.sync GEMM ----------------
// C[M,N] = (Ah+Al)[M,K] @ (Bh+Bl)[N,K]^T   (both operands K-major)
// MODE 0: +bias, split bf16 out, row-major (q/k)
// MODE 1: +bias, split bf16 out, transposed per batch (v^T) via smem bounce
// MODE 2/3: fp32 out (scores / final)
template <int MODE>
__global__ __launch_bounds__(256, 1)
void gemm_bf16x3(const __nv_bfloat16* __restrict__ Ah, const __nv_bfloat16* __restrict__ Al, int lda,
                 const __nv_bfloat16* __restrict__ Bh, const __nv_bfloat16* __restrict__ Bl, int ldb,
                 const float* __restrict__ bias,
                 float* __restrict__ Fo, __nv_bfloat16* __restrict__ Oh, __nv_bfloat16* __restrict__ Ol,
                 int ldo, int K, long long sA, long long sB, long long sO)
{
    extern __shared__ __align__(1024) char smem[];
    const uint32_t smb = smem_u32(smem);
    const int tid  = threadIdx.x;
    const int lane = tid & 31;
    const int wid  = tid >> 5;
    const int wm   = wid & 3;          // 4 warps along M
    const int wn   = wid >> 2;         // 2 warps along N
    const int z = blockIdx.z;
    const int rowBase = blockIdx.y * TMt;
    const int colBase = blockIdx.x * TNt;

    const __nv_bfloat16* Ahp = Ah + sA * z + (long long)rowBase * lda;
    const __nv_bfloat16* Alp = Al + sA * z + (long long)rowBase * lda;
    const __nv_bfloat16* Bhp = Bh + sB * z + (long long)colBase * ldb;
    const __nv_bfloat16* Blp = Bl + sB * z + (long long)colBase * ldb;

    auto load_stage = [&](int st, int kt) {
        const int k0 = kt * TKt;
        const uint32_t sb = smb + st * STAGE_BYTES;
#pragma unroll
        for (int i = 0; i < 4; i++) {
            const int c  = tid + i * 256;      // 0..1023
            const int r  = c >> 3;
            const int cc = c & 7;
            const uint32_t sw = sw128((uint32_t)(r * 128 + cc * 16));
            const long long ga = (long long)r * lda + k0 + cc * 8;
            const long long gb = (long long)r * ldb + k0 + cc * 8;
            cp16(sb + OFF_AH + sw, Ahp + ga);
            cp16(sb + OFF_AL + sw, Alp + ga);
            cp16(sb + OFF_BH + sw, Bhp + gb);
            cp16(sb + OFF_BL + sw, Blp + gb);
        }
        CP_COMMIT();
    };

    float acc[2][8][4];
#pragma unroll
    for (int a = 0; a < 2; a++)
#pragma unroll
        for (int b = 0; b < 8; b++)
#pragma unroll
            for (int c = 0; c < 4; c++) acc[a][b][c] = 0.f;

    const int nk = K / TKt;
    load_stage(0, 0);
    load_stage(1, 1);

    for (int t = 0; t < nk; t++) {
        if (t + 1 < nk) { CP_WAIT1(); } else { CP_WAIT0(); }
        __syncthreads();

        const uint32_t sb = smb + (t % NSTAGE) * STAGE_BYTES;
#pragma unroll
        for (int kk = 0; kk < TKt; kk += 16) {
            uint32_t ah[2][4], al[2][4], bh[4][4], bl[4][4];
#pragma unroll
            for (int mt = 0; mt < 2; mt++) {
                const int r = wm * 32 + mt * 16 + (lane & 15);
                const uint32_t sw = sw128((uint32_t)(r * 128 + kk * 2 + ((lane >> 4) << 4)));
                ldsm_x4(ah[mt], sb + OFF_AH + sw);
                ldsm_x4(al[mt], sb + OFF_AL + sw);
            }
#pragma unroll
            for (int np = 0; np < 4; np++) {
                const int r = wn * 64 + np * 16 + (lane & 7) + ((lane >> 4) << 3);
                const uint32_t sw = sw128((uint32_t)(r * 128 + kk * 2 + (((lane >> 3) & 1) << 4)));
                ldsm_x4(bh[np], sb + OFF_BH + sw);
                ldsm_x4(bl[np], sb + OFF_BL + sw);
            }
#pragma unroll
            for (int mt = 0; mt < 2; mt++)
#pragma unroll
                for (int np = 0; np < 4; np++) {
                    mma_16816(acc[mt][np * 2 + 0], ah[mt], bh[np][0], bh[np][1]);
                    mma_16816(acc[mt][np * 2 + 0], ah[mt], bl[np][0], bl[np][1]);
                    mma_16816(acc[mt][np * 2 + 0], al[mt], bh[np][0], bh[np][1]);
                    mma_16816(acc[mt][np * 2 + 1], ah[mt], bh[np][2], bh[np][3]);
                    mma_16816(acc[mt][np * 2 + 1], ah[mt], bl[np][2], bl[np][3]);
                    mma_16816(acc[mt][np * 2 + 1], al[mt], bh[np][2], bh[np][3]);
                }
        }
        __syncthreads();
        if (t + 2 < nk) load_stage((t + 2) % NSTAGE, t + 2);
    }

    // ---------------- epilogue ----------------
    const int mB = wm * 32;
    const int nB = wn * 64;

    if (MODE == 0 || MODE == 2 || MODE == 3) {
#pragma unroll
        for (int mt = 0; mt < 2; mt++)
#pragma unroll
            for (int nt = 0; nt < 8; nt++)
#pragma unroll
                for (int h = 0; h < 2; h++) {
                    const int m = rowBase + mB + mt * 16 + (lane >> 2) + h * 8;
                    const int n = colBase + nB + nt * 8 + ((lane & 3) << 1);
                    float v0 = acc[mt][nt][h * 2 + 0];
                    float v1 = acc[mt][nt][h * 2 + 1];
                    if (MODE == 0) {
                        v0 += __ldg(&bias[n]);
                        v1 += __ldg(&bias[n + 1]);
                        const __nv_bfloat16 h0 = __float2bfloat16(v0);
                        const __nv_bfloat16 h1 = __float2bfloat16(v1);
                        __nv_bfloat162 hv, lv;
                        hv.x = h0; hv.y = h1;
                        lv.x = __float2bfloat16(v0 - __bfloat162float(h0));
                        lv.y = __float2bfloat16(v1 - __bfloat162float(h1));
                        const long long o = (long long)m * ldo + n;
                        *(__nv_bfloat162*)(Oh + o) = hv;
                        *(__nv_bfloat162*)(Ol + o) = lv;
                    } else {
                        float2 fv; fv.x = v0; fv.y = v1;
                        *(float2*)(Fo + sO * z + (long long)m * ldo + n) = fv;
                    }
                }
    } else {
        // MODE 1: bounce through smem, emit coalesced V^T
        __nv_bfloat16* Th = (__nv_bfloat16*)smem;                    // [128][136]
        __nv_bfloat16* Tl = (__nv_bfloat16*)(smem + 128 * 136 * 2);
        __syncthreads();   // stage smem no longer needed
#pragma unroll
        for (int mt = 0; mt < 2; mt++)
#pragma unroll
            for (int nt = 0; nt < 8; nt++)
#pragma unroll
                for (int h = 0; h < 2; h++) {
                    const int ml = mB + mt * 16 + (lane >> 2) + h * 8;
                    const int nl = nB + nt * 8 + ((lane & 3) << 1);
#pragma unroll
                    for (int j = 0; j < 2; j++) {
                        float v = acc[mt][nt][h * 2 + j] + __ldg(&bias[colBase + nl + j]);
                        const __nv_bfloat16 hb = __float2bfloat16(v);
                        Th[(nl + j) * 136 + ml] = hb;
                        Tl[(nl + j) * 136 + ml] = __float2bfloat16(v - __bfloat162float(hb));
                    }
                }
        __syncthreads();
        const int b   = rowBase >> 11;
        const int pos = rowBase & (SEQ - 1);
        const long long bb = (long long)b * DIM * SEQ + pos;
        for (int c = tid; c < 128 * 16; c += 256) {
            const int nr = c >> 4;
            const int cc = c & 15;
            const long long go = bb + (long long)(colBase + nr) * SEQ + cc * 8;
            *(uint4*)(Oh + go) = *(uint4*)(Th + nr * 136 + cc * 8);
            *(uint4*)(Ol + go) = *(uint4*)(Tl + nr * 136 + cc * 8);
        }
    }
}

// ---------------- prep kernels ----------------
__global__ void split_kernel(const float* __restrict__ src,
                             __nv_bfloat16* __restrict__ hi, __nv_bfloat16* __restrict__ lo,
                             long long n2)
{
    const long long stride = (long long)gridDim.x * blockDim.x;
    for (long long i = (long long)blockIdx.x * blockDim.x + threadIdx.x; i < n2; i += stride) {
        const float2 a = ((const float2*)src)[i];
        __nv_bfloat162 h, l;
        h.x = __float2bfloat16(a.x);
        h.y = __float2bfloat16(a.y);
        l.x = __float2bfloat16(a.x - __bfloat162float(h.x));
        l.y = __float2bfloat16(a.y - __bfloat162float(h.y));
        ((__nv_bfloat162*)hi)[i] = h;
        ((__nv_bfloat162*)lo)[i] = l;
    }
}

// transpose [DIM,DIM] fp32 W -> split bf16 Wt (Wt[n][k] = W[k][n])
__global__ void wtrans_kernel(const float* __restrict__ W,
                              __nv_bfloat16* __restrict__ Th, __nv_bfloat16* __restrict__ Tl)
{
    __shared__ float t[32][33];
    const int x = blockIdx.x * 32 + threadIdx.x;
    const int y0 = blockIdx.y * 32;
#pragma unroll
    for (int i = 0; i < 32; i += 8)
        t[threadIdx.y + i][threadIdx.x] = W[(long long)(y0 + threadIdx.y + i) * DIM + x];
    __syncthreads();
#pragma unroll
    for (int i = 0; i < 32; i += 8) {
        const float val = t[threadIdx.x][threadIdx.y + i];
        const int n = blockIdx.x * 32 + threadIdx.y + i;
        const int k = y0 + threadIdx.x;
        const __nv_bfloat16 h = __float2bfloat16(val);
        const long long o = (long long)n * DIM + k;
        Th[o] = h;
        Tl[o] = __float2bfloat16(val - __bfloat162float(h));
    }
}

// row softmax (with 1/sqrt(D) scale) -> split bf16 probs
__global__ void softmax_split_kernel(const float* __restrict__ S,
                                     __nv_bfloat16* __restrict__ Ph, __nv_bfloat16* __restrict__ Pl)
{
    const long long row = blockIdx.x;
    const float* p = S + row * (long long)SEQ;
    const int t = threadIdx.x;

    __shared__ float sh[32];
    const float scale = 0.03125f;

    float v[8];
    float mx = -INFINITY;
#pragma unroll
    for (int i = 0; i < 8; i++) {
        v[i] = p[t + i * 256] * scale;
        mx = fmaxf(mx, v[i]);
    }
#pragma unroll
    for (int o = 16; o; o >>= 1) mx = fmaxf(mx, __shfl_xor_sync(0xffffffffu, mx, o));
    if ((t & 31) == 0) sh[t >> 5] = mx;
    __syncthreads();
    if (t == 0) {
        float m = sh[0];
#pragma unroll
        for (int w = 1; w < 8; w++) m = fmaxf(m, sh[w]);
        sh[0] = m;
    }
    __syncthreads();
    mx = sh[0];

    float sum = 0.f;
#pragma unroll
    for (int i = 0; i < 8; i++) {
        v[i] = expf(v[i] - mx);
        sum += v[i];
    }
#pragma unroll
    for (int o = 16; o; o >>= 1) sum += __shfl_xor_sync(0xffffffffu, sum, o);
    __syncthreads();
    if ((t & 31) == 0) sh[t >> 5] = sum;
    __syncthreads();
    if (t == 0) {
        float s = 0.f;
#pragma unroll
        for (int w = 0; w < 8; w++) s += sh[w];
        sh[0] = s;
    }
    __syncthreads();
    const float inv = 1.0f / sh[0];

#pragma unroll
    for (int i = 0; i < 8; i++) {
        const float pv = v[i] * inv;
        const __nv_bfloat16 h = __float2bfloat16(pv);
        const long long o = row * (long long)SEQ + t + i * 256;
        Ph[o] = h;
        Pl[o] = __float2bfloat16(pv - __bfloat162float(h));
    }
}

// ---------------- launch ----------------
extern "C" void kernel_launch(void* const* d_in, const int* in_sizes, int n_in,
                              void* d_out, int out_size)
{
    const float* x  = (const float*)d_in[0];
    const float* Wq = (const float*)d_in[1];
    const float* bq = (const float*)d_in[2];
    const float* Wk = (const float*)d_in[3];
    const float* bk = (const float*)d_in[4];
    const float* Wv = (const float*)d_in[5];
    const float* bv = (const float*)d_in[6];
    float* out = (float*)d_out;

    __nv_bfloat16 *xh, *xl, *wth, *wtl, *qh, *ql, *kh, *kl, *vth, *vtl, *ph, *pl;
    float* s;
    cudaGetSymbolAddress((void**)&xh,  g_xh);
    cudaGetSymbolAddress((void**)&xl,  g_xl);
    cudaGetSymbolAddress((void**)&wth, g_wth);
    cudaGetSymbolAddress((void**)&wtl, g_wtl);
    cudaGetSymbolAddress((void**)&qh,  g_qh);
    cudaGetSymbolAddress((void**)&ql,  g_ql);
    cudaGetSymbolAddress((void**)&kh,  g_kh);
    cudaGetSymbolAddress((void**)&kl,  g_kl);
    cudaGetSymbolAddress((void**)&vth, g_vth);
    cudaGetSymbolAddress((void**)&vtl, g_vtl);
    cudaGetSymbolAddress((void**)&s,   g_s);
    cudaGetSymbolAddress((void**)&ph,  g_ph);
    cudaGetSymbolAddress((void**)&pl,  g_pl);

    cudaFuncSetAttribute(gemm_bf16x3<0>, cudaFuncAttributeMaxDynamicSharedMemorySize, SMEM_TOTAL);
    cudaFuncSetAttribute(gemm_bf16x3<1>, cudaFuncAttributeMaxDynamicSharedMemorySize, SMEM_TOTAL);
    cudaFuncSetAttribute(gemm_bf16x3<2>, cudaFuncAttributeMaxDynamicSharedMemorySize, SMEM_TOTAL);
    cudaFuncSetAttribute(gemm_bf16x3<3>, cudaFuncAttributeMaxDynamicSharedMemorySize, SMEM_TOTAL);

    // prep: split x, transpose+split weights
    split_kernel<<<4096, 256>>>(x, xh, xl, (long long)BN_ROWS * DIM / 2);
    {
        dim3 g(DIM / 32, DIM / 32), b(32, 8);
        wtrans_kernel<<<g, b>>>(Wq, wth, wtl);
        wtrans_kernel<<<g, b>>>(Wk, wth + (size_t)DIM * DIM, wtl + (size_t)DIM * DIM);
        wtrans_kernel<<<g, b>>>(Wv, wth + 2 * (size_t)DIM * DIM, wtl + 2 * (size_t)DIM * DIM);
    }

    const dim3 blk(256);
    const long long sQK = (long long)SEQ * DIM;
    const long long sSS = (long long)SEQ * SEQ;

    // QKV projections: [16384,1024] x [1024,1024]^T(k-major)
    {
        dim3 g(DIM / TNt, BN_ROWS / TMt, 1);   // (8, 128, 1)
        gemm_bf16x3<0><<<g, blk, SMEM_TOTAL>>>(xh, xl, DIM, wth, wtl, DIM, bq,
                                               nullptr, qh, ql, DIM, DIM, 0, 0, 0);
        gemm_bf16x3<0><<<g, blk, SMEM_TOTAL>>>(xh, xl, DIM, wth + (size_t)DIM * DIM, wtl + (size_t)DIM * DIM, DIM, bk,
                                               nullptr, kh, kl, DIM, DIM, 0, 0, 0);
        gemm_bf16x3<1><<<g, blk, SMEM_TOTAL>>>(xh, xl, DIM, wth + 2 * (size_t)DIM * DIM, wtl + 2 * (size_t)DIM * DIM, DIM, bv,
                                               nullptr, vth, vtl, 0, DIM, 0, 0, 0);
    }
    // scores = Q @ K^T
    {
        dim3 g(SEQ / TNt, SEQ / TMt, BATCH);   // (16, 16, 8)
        gemm_bf16x3<2><<<g, blk, SMEM_TOTAL>>>(qh, ql, DIM, kh, kl, DIM, nullptr,
                                               s, nullptr, nullptr, SEQ, DIM, sQK, sQK, sSS);
    }
    // softmax + split
    softmax_split_kernel<<<BATCH * SEQ, 256>>>(s, ph, pl);
    // out = P @ V   (B = V^T, K-major, K=SEQ)
    {
        dim3 g(DIM / TNt, SEQ / TMt, BATCH);   // (8, 16, 8)
        gemm_bf16x3<3><<<g, blk, SMEM_TOTAL>>>(ph, pl, SEQ, vth, vtl, SEQ, nullptr,
                                               out, nullptr, nullptr, DIM, SEQ, sSS, (long long)DIM * SEQ, sQK);
    }
}